// round 15
// baseline (speedup 1.0000x reference)
#include <cuda_runtime.h>
#include <cuda_bf16.h>
#include <cstdint>
#include <cstddef>

// ---------------- problem constants ----------------
#define BATCH 2
#define TSEQ  1024
#define MROWS (BATCH*TSEQ)      // 2048
#define DMODEL 768
#define NHEAD 12
#define DHEAD 64
#define DMLP  3072
#define NLAYER 12
#define VOCAB 50257
#define DQKV  (3*DMODEL)        // 2304

// ---------------- scratch (static device globals; no allocation) ----------------
__device__ float g_x  [MROWS*DMODEL];          // residual stream (fp32)
__device__ __nv_bfloat16 g_qh[MROWS*DQKV],   g_qlo[MROWS*DQKV];    // qkv split
__device__ __nv_bfloat16 g_hh[MROWS*DMODEL], g_hl[MROWS*DMODEL];   // LN out split
__device__ __nv_bfloat16 g_zh[MROWS*DMODEL], g_zl[MROWS*DMODEL];   // attn out split
__device__ __nv_bfloat16 g_mh[MROWS*DMLP],   g_ml[MROWS*DMLP];     // MLP hidden split

// split+transposed weights, [N][K] K-major bf16 planes
__device__ __nv_bfloat16 g_wqkv_h[NLAYER*DQKV*DMODEL],  g_wqkv_l[NLAYER*DQKV*DMODEL];
__device__ __nv_bfloat16 g_wo_h  [NLAYER*DMODEL*DMODEL],g_wo_l  [NLAYER*DMODEL*DMODEL];
__device__ __nv_bfloat16 g_w1_h  [NLAYER*DMLP*DMODEL],  g_w1_l  [NLAYER*DMLP*DMODEL];
__device__ __nv_bfloat16 g_w2_h  [NLAYER*DMODEL*DMLP],  g_w2_l  [NLAYER*DMODEL*DMLP];
__device__ __nv_bfloat16 g_wu_h  [VOCAB*DMODEL],        g_wu_l  [VOCAB*DMODEL];
__device__ float g_bqkv[NLAYER*DQKV];

// ---------------- PTX helpers (plain sm_80+ features only) ----------------
__device__ __forceinline__ uint32_t smem_u32(const void* p){
    uint32_t a;
    asm("{ .reg .u64 t; cvta.to.shared.u64 t, %1; cvt.u32.u64 %0, t; }" : "=r"(a) : "l"(p));
    return a;
}
__device__ __forceinline__ void cpa16(uint32_t dst, const void* src, uint32_t srcsize){
    asm volatile("cp.async.cg.shared.global [%0], [%1], 16, %2;"
                 :: "r"(dst), "l"(src), "r"(srcsize) : "memory");
}
__device__ __forceinline__ void cpa_commit(){
    asm volatile("cp.async.commit_group;" ::: "memory");
}
__device__ __forceinline__ void cpa_wait1(){
    asm volatile("cp.async.wait_group 1;" ::: "memory");
}
__device__ __forceinline__ void cpa_wait0(){
    asm volatile("cp.async.wait_group 0;" ::: "memory");
}
__device__ __forceinline__ void ldsm4(uint32_t* r, uint32_t addr){
    asm volatile("ldmatrix.sync.aligned.m8n8.x4.shared.b16 {%0,%1,%2,%3}, [%4];"
                 : "=r"(r[0]), "=r"(r[1]), "=r"(r[2]), "=r"(r[3]) : "r"(addr));
}
__device__ __forceinline__ void ldsm4t(uint32_t* r, uint32_t addr){
    asm volatile("ldmatrix.sync.aligned.m8n8.x4.trans.shared.b16 {%0,%1,%2,%3}, [%4];"
                 : "=r"(r[0]), "=r"(r[1]), "=r"(r[2]), "=r"(r[3]) : "r"(addr));
}
__device__ __forceinline__ void mma_bf16(float* c, const uint32_t* a, const uint32_t* b){
    asm volatile("mma.sync.aligned.m16n8k16.row.col.f32.bf16.bf16.f32 "
                 "{%0,%1,%2,%3}, {%4,%5,%6,%7}, {%8,%9}, {%0,%1,%2,%3};"
                 : "+f"(c[0]), "+f"(c[1]), "+f"(c[2]), "+f"(c[3])
                 : "r"(a[0]), "r"(a[1]), "r"(a[2]), "r"(a[3]), "r"(b[0]), "r"(b[1]));
}
#define SMEM_SWIZZLE_128B(o) ((o) ^ (((o) >> 3) & 0x70))

// ---------------- small helpers ----------------
__device__ __forceinline__ float gelu_f(float x){
    return 0.5f * x * (1.0f + erff(x * 0.70710678118654752440f));
}
__device__ __forceinline__ void split2(float v, __nv_bfloat16& h, __nv_bfloat16& l){
    h = __float2bfloat16(v);
    l = __float2bfloat16(v - __bfloat162float(h));
}
__device__ __forceinline__ uint32_t pack_bf16(float a, float b){
    __nv_bfloat162 t = __floats2bfloat162_rn(a, b);   // low = a, high = b
    return *(uint32_t*)&t;
}

// ---------------- uber weight split+transpose (single launch) ----------------
// src[K][N] fp32 -> dst planes [N][K] bf16 (hi/lo), 32x32 tiles
__global__ void tsplit_all(const float* __restrict__ Wq, const float* __restrict__ Wk,
                           const float* __restrict__ Wv, const float* __restrict__ Wo,
                           const float* __restrict__ W1, const float* __restrict__ W2,
                           const float* __restrict__ Wu,
                           __nv_bfloat16* wqh, __nv_bfloat16* wql,
                           __nv_bfloat16* woh, __nv_bfloat16* wol,
                           __nv_bfloat16* w1h, __nv_bfloat16* w1l,
                           __nv_bfloat16* w2h, __nv_bfloat16* w2l,
                           __nv_bfloat16* wuh, __nv_bfloat16* wul)
{
    const int T0 = 24*24*12;          // 6912 tiles per D×D weight
    const int TW = 24*96*12;          // 27648 for W1 / W2
    int id = blockIdx.x;
    const float* src; __nv_bfloat16 *dh, *dl;
    long srcLS, dstLS; int rowOff = 0, ld, K, N;
    int l, kti, nti;
    if (id < 4*T0){
        int seg = id / T0, r = id % T0;
        l = r / 576; int r2 = r % 576; kti = r2 / 24; nti = r2 % 24;
        K = 768; N = 768; srcLS = 589824;
        if (seg < 3){
            src = (seg==0)?Wq:(seg==1)?Wk:Wv;
            dh = wqh; dl = wql; dstLS = 1769472; ld = 768; rowOff = seg*768;
        } else {
            src = Wo; dh = woh; dl = wol; dstLS = 589824; ld = 768;
        }
    } else if (id < 4*T0 + TW){
        int r = id - 4*T0;
        l = r / 2304; int r2 = r % 2304; kti = r2 / 96; nti = r2 % 96;
        src = W1; dh = w1h; dl = w1l; srcLS = 2359296; dstLS = 2359296;
        ld = 768; K = 768; N = 3072;
    } else if (id < 4*T0 + 2*TW){
        int r = id - 4*T0 - TW;
        l = r / 2304; int r2 = r % 2304; kti = r2 / 24; nti = r2 % 24;
        src = W2; dh = w2h; dl = w2l; srcLS = 2359296; dstLS = 2359296;
        ld = 3072; K = 3072; N = 768;
    } else {
        int r = id - 4*T0 - 2*TW;
        l = 0; kti = r / 1571; nti = r % 1571;
        src = Wu; dh = wuh; dl = wul; srcLS = 0; dstLS = 0;
        ld = 768; K = 768; N = VOCAB;
    }
    const int k0 = kti*32, n0 = nti*32;
    __shared__ float t[32][33];
    int tx = threadIdx.x & 31, ty = threadIdx.x >> 5;
    const float* s = src + (size_t)l * srcLS;
    #pragma unroll
    for (int i = ty; i < 32; i += 8){
        int k = k0 + i, n = n0 + tx;
        t[i][tx] = (k < K && n < N) ? s[(size_t)k * N + n] : 0.f;
    }
    __syncthreads();
    __nv_bfloat16* ph = dh + (size_t)l * dstLS;
    __nv_bfloat16* pl = dl + (size_t)l * dstLS;
    #pragma unroll
    for (int i = ty; i < 32; i += 8){
        int n = n0 + i, k = k0 + tx;
        if (n < N && k < K){
            float v = t[tx][i];
            __nv_bfloat16 h, lo; split2(v, h, lo);
            size_t off = (size_t)(rowOff + n) * ld + k;
            ph[off] = h; pl[off] = lo;
        }
    }
}

__global__ void bcat_k(const float* __restrict__ bq, const float* __restrict__ bk,
                       const float* __restrict__ bv, float* __restrict__ dst)
{
    int l = blockIdx.y;
    int i = blockIdx.x * 256 + threadIdx.x;
    if (i < DQKV){
        float v = (i < 768) ? bq[l*768 + i] : (i < 1536) ? bk[l*768 + i - 768]
                                                         : bv[l*768 + i - 1536];
        dst[l*DQKV + i] = v;
    }
}

// ---------------- embedding ----------------
__global__ void embed_k(const int* __restrict__ ids, const float* __restrict__ emb,
                        const float* __restrict__ pos, float* __restrict__ x)
{
    int row = blockIdx.x, t = row % TSEQ, id = ids[row];
    const float* er = emb + (size_t)id * DMODEL;
    const float* pr = pos + (size_t)t  * DMODEL;
    float* xr = x + (size_t)row * DMODEL;
    int tid = threadIdx.x;
    xr[tid]       = er[tid]       + pr[tid];
    xr[tid + 256] = er[tid + 256] + pr[tid + 256];
    xr[tid + 512] = er[tid + 512] + pr[tid + 512];
}

// ---------------- layernorm -> bf16 hi/lo split ----------------
__global__ void ln_split_k(const float* __restrict__ x, const float* __restrict__ g,
                           const float* __restrict__ b,
                           __nv_bfloat16* __restrict__ oh, __nv_bfloat16* __restrict__ ol)
{
    __shared__ float red0[8], red1[8];
    int row = blockIdx.x, tid = threadIdx.x;
    const float* xr = x + (size_t)row * DMODEL;
    float v0 = xr[tid], v1 = xr[tid + 256], v2 = xr[tid + 512];
    float s  = v0 + v1 + v2;
    float s2 = v0*v0 + v1*v1 + v2*v2;
    #pragma unroll
    for (int off = 16; off; off >>= 1){
        s  += __shfl_xor_sync(0xffffffffu, s,  off);
        s2 += __shfl_xor_sync(0xffffffffu, s2, off);
    }
    int w = tid >> 5;
    if ((tid & 31) == 0){ red0[w] = s; red1[w] = s2; }
    __syncthreads();
    if (tid < 32){
        s  = (tid < 8) ? red0[tid] : 0.f;
        s2 = (tid < 8) ? red1[tid] : 0.f;
        #pragma unroll
        for (int off = 4; off; off >>= 1){
            s  += __shfl_xor_sync(0xffffffffu, s,  off);
            s2 += __shfl_xor_sync(0xffffffffu, s2, off);
        }
        if (tid == 0){ red0[0] = s; red1[0] = s2; }
    }
    __syncthreads();
    float mean = red0[0] * (1.f/768.f);
    float var  = red1[0] * (1.f/768.f) - mean * mean;
    float r    = rsqrtf(var + 1e-5f);
    size_t base = (size_t)row * DMODEL;
    #pragma unroll
    for (int e = 0; e < 3; ++e){
        int idx = tid + e*256;
        float vv = (e==0?v0:(e==1?v1:v2));
        float y = (vv - mean) * r * g[idx] + b[idx];
        __nv_bfloat16 h, lo; split2(y, h, lo);
        oh[base + idx] = h; ol[base + idx] = lo;
    }
}

// ---------------- mma.sync bf16-split GEMM (16 warps) ----------------
// C[M,N] = epi( (Ah+Al) * (Bh+Bl)^T + bias )   A:[M][K] planes, B:[N][K] planes.
// EPI: 0 = fp32 out ; 2 = fp32 out + residual ; 3 = GELU -> bf16 split out ;
//      4 = bias only -> bf16 split out
#define WS_THREADS 512
#define WS_NSTAGE 3
#define WS_STAGE_BYTES 65536
#define WS_SMEM (WS_NSTAGE*WS_STAGE_BYTES)

template<int EPI>
__global__ __launch_bounds__(WS_THREADS, 1)
void gemm_ws(const __nv_bfloat16* __restrict__ Ah, const __nv_bfloat16* __restrict__ Al,
             const __nv_bfloat16* __restrict__ Bh, const __nv_bfloat16* __restrict__ Bl,
             const float* __restrict__ bias, const float* __restrict__ res,
             float* __restrict__ C, __nv_bfloat16* __restrict__ Ch,
             __nv_bfloat16* __restrict__ Cl, int M, int N, int K)
{
    extern __shared__ char smem[];
    const uint32_t sb = smem_u32(smem);
    const int tid = threadIdx.x, wid = tid >> 5, lane = tid & 31;
    const int warp_m = wid >> 2;       // 0..3 -> 32 rows each
    const int warp_n = wid & 3;        // 0..3 -> 32 cols each
    const int m0 = blockIdx.y * 128, n0 = blockIdx.x * 128;

    float acc[8][4];                   // [mt(2) * nt(4)]
    #pragma unroll
    for (int i = 0; i < 8; i++)
        #pragma unroll
        for (int j = 0; j < 4; j++) acc[i][j] = 0.f;

    const int nch = K >> 6;

    auto load_stage = [&](int st, int k0){
        const uint32_t s0 = sb + (uint32_t)st * WS_STAGE_BYTES;
        #pragma unroll
        for (int it = 0; it < 2; ++it){
            int idx = it * 512 + tid;            // 0..1023
            int row = idx >> 3, ch = idx & 7;
            uint32_t off = SMEM_SWIZZLE_128B(row*128 + ch*16);
            const size_t aoff = (size_t)(m0 + row) * K + k0 + ch*8;
            cpa16(s0 +         off, Ah + aoff, 16);
            cpa16(s0 + 16384 + off, Al + aoff, 16);
            int brow = n0 + row;
            uint32_t sz = (brow < N) ? 16u : 0u;
            if (brow >= N) brow = N - 1;
            const size_t boff = (size_t)brow * K + k0 + ch*8;
            cpa16(s0 + 32768 + off, Bh + boff, sz);
            cpa16(s0 + 49152 + off, Bl + boff, sz);
        }
        cpa_commit();
    };

    auto compute_stage = [&](int st){
        const uint32_t sAh = sb + (uint32_t)st * WS_STAGE_BYTES;
        const uint32_t sAl = sAh + 16384;
        const uint32_t sBh = sAh + 32768;
        const uint32_t sBl = sAh + 49152;
        #pragma unroll
        for (int ks = 0; ks < 4; ++ks){
            uint32_t ah[2][4], al[2][4], bh[4][2], bl[4][2];
            const int arow = warp_m*32 + (lane & 7) + ((lane >> 3) & 1) * 8;
            const int akc  = ks*16 + ((lane >> 4) & 1) * 8;
            #pragma unroll
            for (int mt = 0; mt < 2; ++mt){
                uint32_t off = SMEM_SWIZZLE_128B((arow + mt*16)*128 + akc*2);
                ldsm4(ah[mt], sAh + off);
                ldsm4(al[mt], sAl + off);
            }
            const int brow0 = warp_n*32 + ((lane >> 4) & 1) * 8 + (lane & 7);
            const int bkc   = ks*16 + ((lane >> 3) & 1) * 8;
            #pragma unroll
            for (int nq = 0; nq < 2; ++nq){
                uint32_t off = SMEM_SWIZZLE_128B((brow0 + nq*16)*128 + bkc*2);
                uint32_t r[4];
                ldsm4(r, sBh + off);
                bh[2*nq][0] = r[0]; bh[2*nq][1] = r[1];
                bh[2*nq+1][0] = r[2]; bh[2*nq+1][1] = r[3];
                ldsm4(r, sBl + off);
                bl[2*nq][0] = r[0]; bl[2*nq][1] = r[1];
                bl[2*nq+1][0] = r[2]; bl[2*nq+1][1] = r[3];
            }
            #pragma unroll
            for (int mt = 0; mt < 2; ++mt)
                #pragma unroll
                for (int nt = 0; nt < 4; ++nt){
                    float* c = acc[mt*4 + nt];
                    mma_bf16(c, ah[mt], bh[nt]);
                    mma_bf16(c, ah[mt], bl[nt]);
                    mma_bf16(c, al[mt], bh[nt]);
                }
        }
    };

    load_stage(0, 0);
    load_stage(1, 64);
    for (int c = 0; c < nch; ++c){
        if (c + 1 < nch) cpa_wait1(); else cpa_wait0();
        __syncthreads();
        int p = c + WS_NSTAGE - 1;
        if (p < nch) load_stage(p % WS_NSTAGE, p * 64);
        else cpa_commit();
        compute_stage(c % WS_NSTAGE);
    }

    const int lr = lane >> 2, lc = (lane & 3) * 2;
    const bool nvec = ((N & 1) == 0);
    #pragma unroll
    for (int mt = 0; mt < 2; ++mt){
        #pragma unroll
        for (int nt = 0; nt < 4; ++nt){
            const float* cfr = acc[mt*4 + nt];
            const int n = n0 + warp_n*32 + nt*8 + lc;
            #pragma unroll
            for (int half = 0; half < 2; ++half){
                const int m = m0 + warp_m*32 + mt*16 + lr + half*8;
                float v0 = cfr[half*2 + 0];
                float v1 = cfr[half*2 + 1];
                if (EPI == 3 || EPI == 4){
                    v0 += bias[n]; v1 += bias[n+1];
                    if (EPI == 3){ v0 = gelu_f(v0); v1 = gelu_f(v1); }
                    __nv_bfloat16 h0, l0, h1, l1;
                    split2(v0, h0, l0); split2(v1, h1, l1);
                    __nv_bfloat162 hp; hp.x = h0; hp.y = h1;
                    __nv_bfloat162 lp; lp.x = l0; lp.y = l1;
                    *(__nv_bfloat162*)(Ch + (size_t)m * N + n) = hp;
                    *(__nv_bfloat162*)(Cl + (size_t)m * N + n) = lp;
                } else {
                    if (n < N) v0 += bias[n];
                    if (n + 1 < N) v1 += bias[n+1];
                    if (EPI == 2){
                        const float2 r2 = *(const float2*)(res + (size_t)m * N + n);
                        v0 += r2.x; v1 += r2.y;
                    }
                    if (nvec && (n + 1 < N)){
                        float2 o2; o2.x = v0; o2.y = v1;
                        *(float2*)(C + (size_t)m * N + n) = o2;
                    } else {
                        if (n < N)     C[(size_t)m * N + n]     = v0;
                        if (n + 1 < N) C[(size_t)m * N + n + 1] = v1;
                    }
                }
            }
        }
    }
}

// ---------------- tensor-core flash attention (bf16 hi/lo split, 3-pass) ----------------
// Input: qkv planes [M][2304] (hi/lo). Output: Z planes [M][768] (hi/lo).
// CTA: 64 q rows, 4 warps x 16 rows. KV tiles of 64. smem = 48KB.
#define AT_SMEM 49152
__global__ __launch_bounds__(128)
void attn_tc(const __nv_bfloat16* __restrict__ Xh, const __nv_bfloat16* __restrict__ Xl,
             __nv_bfloat16* __restrict__ Zh, __nv_bfloat16* __restrict__ Zl)
{
    extern __shared__ char sm[];
    const uint32_t sb = smem_u32(sm);
    // layout: Qh 0, Ql 8192, Kh 16384, Kl 24576, Vh 32768, Vl 40960
    const int tid = threadIdx.x, warp = tid >> 5, lane = tid & 31;
    const int qt = blockIdx.x, bh = blockIdx.y;
    const int b = bh / NHEAD, h = bh % NHEAD;
    const int q0 = qt * 64;
    const size_t rowbase = (size_t)b * TSEQ;
    const int colQ = h*DHEAD, colK = DMODEL + h*DHEAD, colV = 2*DMODEL + h*DHEAD;

    // load Q tile (hi/lo)
    #pragma unroll
    for (int it = 0; it < 4; ++it){
        int idx = it*128 + tid;
        int r = idx >> 3, ch = idx & 7;
        uint32_t off = SMEM_SWIZZLE_128B(r*128 + ch*16);
        size_t go = (rowbase + q0 + r) * (size_t)DQKV + colQ + ch*8;
        cpa16(sb +        off, Xh + go, 16);
        cpa16(sb + 8192 + off, Xl + go, 16);
    }
    cpa_commit();

    float mst[2] = {-1e30f, -1e30f}, lst[2] = {0.f, 0.f};
    float zacc[8][4];
    #pragma unroll
    for (int j = 0; j < 8; j++)
        #pragma unroll
        for (int i = 0; i < 4; i++) zacc[j][i] = 0.f;

    cpa_wait0();
    __syncthreads();

    // Q fragments (A operand), 4 k16 slices, hi/lo
    uint32_t qh[4][4], ql[4][4];
    {
        const int arow = warp*16 + (lane & 7) + ((lane >> 3) & 1) * 8;
        #pragma unroll
        for (int ks = 0; ks < 4; ++ks){
            int akc = ks*16 + ((lane >> 4) & 1) * 8;
            uint32_t off = SMEM_SWIZZLE_128B(arow*128 + akc*2);
            ldsm4(qh[ks], sb +        off);
            ldsm4(ql[ks], sb + 8192 + off);
        }
    }

    const int nkt = qt + 1;
    for (int kt = 0; kt < nkt; ++kt){
        const int k0 = kt * 64;
        __syncthreads();          // previous tile's ldsm reads done
        #pragma unroll
        for (int it = 0; it < 4; ++it){
            int idx = it*128 + tid;
            int r = idx >> 3, ch = idx & 7;
            uint32_t off = SMEM_SWIZZLE_128B(r*128 + ch*16);
            size_t gk = (rowbase + k0 + r) * (size_t)DQKV + colK + ch*8;
            size_t gv = (rowbase + k0 + r) * (size_t)DQKV + colV + ch*8;
            cpa16(sb + 16384 + off, Xh + gk, 16);
            cpa16(sb + 24576 + off, Xl + gk, 16);
            cpa16(sb + 32768 + off, Xh + gv, 16);
            cpa16(sb + 40960 + off, Xl + gv, 16);
        }
        cpa_commit(); cpa_wait0();
        __syncthreads();

        // ---- S = Q K^T (3-pass split), per warp: 16 x 64 ----
        float sacc[8][4];
        #pragma unroll
        for (int j = 0; j < 8; j++)
            #pragma unroll
            for (int i = 0; i < 4; i++) sacc[j][i] = 0.f;

        #pragma unroll
        for (int ks = 0; ks < 4; ++ks){
            uint32_t bhf[8][2], blf[8][2];
            const int brow = ((lane >> 4) & 1) * 8 + (lane & 7);
            const int bkc  = ks*16 + ((lane >> 3) & 1) * 8;
            #pragma unroll
            for (int nq = 0; nq < 4; ++nq){
                uint32_t off = SMEM_SWIZZLE_128B((nq*16 + brow)*128 + bkc*2);
                uint32_t r[4];
                ldsm4(r, sb + 16384 + off);
                bhf[2*nq][0] = r[0]; bhf[2*nq][1] = r[1];
                bhf[2*nq+1][0] = r[2]; bhf[2*nq+1][1] = r[3];
                ldsm4(r, sb + 24576 + off);
                blf[2*nq][0] = r[0]; blf[2*nq][1] = r[1];
                blf[2*nq+1][0] = r[2]; blf[2*nq+1][1] = r[3];
            }
            #pragma unroll
            for (int j = 0; j < 8; j++){
                mma_bf16(sacc[j], qh[ks], bhf[j]);
                mma_bf16(sacc[j], qh[ks], blf[j]);
                mma_bf16(sacc[j], ql[ks], bhf[j]);
            }
        }

        // ---- scale + causal mask ----
        const bool diag = (kt == qt);
        const int r0g = q0 + warp*16 + (lane >> 2);
        #pragma unroll
        for (int j = 0; j < 8; j++){
            const int kg = k0 + j*8 + (lane & 3)*2;
            #pragma unroll
            for (int i = 0; i < 4; i++){
                float v = sacc[j][i] * 0.125f;
                if (diag){
                    int kk = kg + (i & 1);
                    int qq = r0g + ((i >= 2) ? 8 : 0);
                    if (kk > qq) v = -1e30f;
                }
                sacc[j][i] = v;
            }
        }

        // ---- online softmax (rows r0, r0+8; reduce over 4-lane col groups) ----
        #pragma unroll
        for (int t = 0; t < 2; ++t){
            float mx = -1e30f;
            #pragma unroll
            for (int j = 0; j < 8; j++)
                mx = fmaxf(mx, fmaxf(sacc[j][2*t], sacc[j][2*t+1]));
            mx = fmaxf(mx, __shfl_xor_sync(0xffffffffu, mx, 1));
            mx = fmaxf(mx, __shfl_xor_sync(0xffffffffu, mx, 2));
            float mn = fmaxf(mst[t], mx);
            float corr = expf(mst[t] - mn);
            mst[t] = mn;
            float rs = 0.f;
            #pragma unroll
            for (int j = 0; j < 8; j++){
                float p0 = expf(sacc[j][2*t]   - mn);
                float p1 = expf(sacc[j][2*t+1] - mn);
                sacc[j][2*t] = p0; sacc[j][2*t+1] = p1;
                rs += p0 + p1;
            }
            rs += __shfl_xor_sync(0xffffffffu, rs, 1);
            rs += __shfl_xor_sync(0xffffffffu, rs, 2);
            lst[t] = lst[t] * corr + rs;
            #pragma unroll
            for (int j = 0; j < 8; j++){
                zacc[j][2*t]   *= corr;
                zacc[j][2*t+1] *= corr;
            }
        }

        // ---- Z += P V  (P split in registers, V via ldsm.trans; 3-pass) ----
        #pragma unroll
        for (int ks2 = 0; ks2 < 4; ++ks2){
            // P fragments from sacc (C-layout -> A-layout identity)
            uint32_t ph[4], pl[4];
            {
                const float* s0 = sacc[2*ks2];
                const float* s1 = sacc[2*ks2+1];
                __nv_bfloat162 h0 = __floats2bfloat162_rn(s0[0], s0[1]);
                __nv_bfloat162 h1 = __floats2bfloat162_rn(s0[2], s0[3]);
                __nv_bfloat162 h2 = __floats2bfloat162_rn(s1[0], s1[1]);
                __nv_bfloat162 h3 = __floats2bfloat162_rn(s1[2], s1[3]);
                ph[0] = *(uint32_t*)&h0; ph[1] = *(uint32_t*)&h1;
                ph[2] = *(uint32_t*)&h2; ph[3] = *(uint32_t*)&h3;
                pl[0] = pack_bf16(s0[0] - __bfloat162float(h0.x), s0[1] - __bfloat162float(h0.y));
                pl[1] = pack_bf16(s0[2] - __bfloat162float(h1.x), s0[3] - __bfloat162float(h1.y));
                pl[2] = pack_bf16(s1[0] - __bfloat162float(h2.x), s1[1] - __bfloat162float(h2.y));
                pl[3] = pack_bf16(s1[2] - __bfloat162float(h3.x), s1[3] - __bfloat162float(h3.y));
            }
            // V fragments (B operand, n=d, k=kv) via trans loads from Vs[kv][d]
            uint32_t vh[8][2], vl[8][2];
            const int vrow = ks2*16 + ((lane >> 3) & 1) * 8 + (lane & 7);
            const int vcb  = ((lane >> 4) & 1) * 8;
            #pragma unroll
            for (int nq = 0; nq < 4; ++nq){
                uint32_t off = SMEM_SWIZZLE_128B(vrow*128 + (nq*16 + vcb)*2);
                uint32_t r[4];
                ldsm4t(r, sb + 32768 + off);
                vh[2*nq][0] = r[0]; vh[2*nq][1] = r[1];
                vh[2*nq+1][0] = r[2]; vh[2*nq+1][1] = r[3];
                ldsm4t(r, sb + 40960 + off);
                vl[2*nq][0] = r[0]; vl[2*nq][1] = r[1];
                vl[2*nq+1][0] = r[2]; vl[2*nq+1][1] = r[3];
            }
            #pragma unroll
            for (int j = 0; j < 8; j++){
                mma_bf16(zacc[j], ph, vh[j]);
                mma_bf16(zacc[j], ph, vl[j]);
                mma_bf16(zacc[j], pl, vh[j]);
            }
        }
    }

    // ---- normalize + write Z as bf16 hi/lo planes [M][768] ----
    #pragma unroll
    for (int t = 0; t < 2; ++t){
        float inv = 1.f / lst[t];
        int qg = q0 + warp*16 + (lane >> 2) + t*8;
        size_t ob = (rowbase + qg) * (size_t)DMODEL + h*DHEAD;
        #pragma unroll
        for (int j = 0; j < 8; j++){
            int d = j*8 + (lane & 3)*2;
            float z0 = zacc[j][2*t]   * inv;
            float z1 = zacc[j][2*t+1] * inv;
            __nv_bfloat16 h0, l0, h1, l1;
            split2(z0, h0, l0); split2(z1, h1, l1);
            __nv_bfloat162 hp; hp.x = h0; hp.y = h1;
            __nv_bfloat162 lp; lp.x = l0; lp.y = l1;
            *(__nv_bfloat162*)(Zh + ob + d) = hp;
            *(__nv_bfloat162*)(Zl + ob + d) = lp;
        }
    }
}

// ---------------- host orchestration ----------------
extern "C" void kernel_launch(void* const* d_in, const int* in_sizes, int n_in,
                              void* d_out, int out_size)
{
    const int*   ids = (const int*)  d_in[0];
    const float* emb = (const float*)d_in[1];
    const float* pos = (const float*)d_in[2];
    const float* Wq  = (const float*)d_in[3],  *bq = (const float*)d_in[4];
    const float* Wk  = (const float*)d_in[5],  *bk = (const float*)d_in[6];
    const float* Wv  = (const float*)d_in[7],  *bv = (const float*)d_in[8];
    const float* Wo  = (const float*)d_in[9],  *bo = (const float*)d_in[10];
    const float* l1g = (const float*)d_in[11], *l1b = (const float*)d_in[12];
    const float* l2g = (const float*)d_in[13], *l2b = (const float*)d_in[14];
    const float* W1  = (const float*)d_in[15], *b1 = (const float*)d_in[16];
    const float* W2  = (const float*)d_in[17], *b2 = (const float*)d_in[18];
    const float* lfg = (const float*)d_in[19], *lfb = (const float*)d_in[20];
    const float* Wu  = (const float*)d_in[21], *bu = (const float*)d_in[22];
    float* out = (float*)d_out;

    float *x, *bqkv;
    __nv_bfloat16 *qh, *qlo, *hh, *hl, *zh, *zl, *mh, *ml;
    __nv_bfloat16 *wqh, *wql, *woh, *wol, *w1h, *w1l, *w2h, *w2l, *wuh, *wul;
    cudaGetSymbolAddress((void**)&x,    g_x);
    cudaGetSymbolAddress((void**)&bqkv, g_bqkv);
    cudaGetSymbolAddress((void**)&qh,   g_qh);  cudaGetSymbolAddress((void**)&qlo, g_qlo);
    cudaGetSymbolAddress((void**)&hh,   g_hh);  cudaGetSymbolAddress((void**)&hl, g_hl);
    cudaGetSymbolAddress((void**)&zh,   g_zh);  cudaGetSymbolAddress((void**)&zl, g_zl);
    cudaGetSymbolAddress((void**)&mh,   g_mh);  cudaGetSymbolAddress((void**)&ml, g_ml);
    cudaGetSymbolAddress((void**)&wqh,  g_wqkv_h); cudaGetSymbolAddress((void**)&wql, g_wqkv_l);
    cudaGetSymbolAddress((void**)&woh,  g_wo_h);   cudaGetSymbolAddress((void**)&wol, g_wo_l);
    cudaGetSymbolAddress((void**)&w1h,  g_w1_h);   cudaGetSymbolAddress((void**)&w1l, g_w1_l);
    cudaGetSymbolAddress((void**)&w2h,  g_w2_h);   cudaGetSymbolAddress((void**)&w2l, g_w2_l);
    cudaGetSymbolAddress((void**)&wuh,  g_wu_h);   cudaGetSymbolAddress((void**)&wul, g_wu_l);

    cudaFuncSetAttribute(gemm_ws<0>, cudaFuncAttributeMaxDynamicSharedMemorySize, WS_SMEM);
    cudaFuncSetAttribute(gemm_ws<2>, cudaFuncAttributeMaxDynamicSharedMemorySize, WS_SMEM);
    cudaFuncSetAttribute(gemm_ws<3>, cudaFuncAttributeMaxDynamicSharedMemorySize, WS_SMEM);
    cudaFuncSetAttribute(gemm_ws<4>, cudaFuncAttributeMaxDynamicSharedMemorySize, WS_SMEM);
    cudaFuncSetAttribute(attn_tc,    cudaFuncAttributeMaxDynamicSharedMemorySize, AT_SMEM);

    const int M = MROWS, D = DMODEL, DM = DMLP, Vn = VOCAB;
    const size_t d2 = (size_t)D * D, dm2 = (size_t)D * DM;

    // single-launch weight split (tiles: 4*6912 + 2*27648 + 37704 = 120648)
    tsplit_all<<<120648, 256>>>(Wq, Wk, Wv, Wo, W1, W2, Wu,
                                wqh, wql, woh, wol, w1h, w1l, w2h, w2l, wuh, wul);
    bcat_k<<<dim3((DQKV + 255)/256, NLAYER), 256>>>(bq, bk, bv, bqkv);
    embed_k<<<M, 256>>>(ids, emb, pos, x);

    const dim3 gQKV(DQKV/128, M/128);      // (18,16)
    const dim3 gD  (D/128,    M/128);      // (6,16)
    const dim3 gM1 (DM/128,   M/128);      // (24,16)
    const dim3 gLM ((Vn + 127)/128, M/128);

    for (int l = 0; l < NLAYER; ++l){
        ln_split_k<<<M, 256>>>(x, l1g + l*D, l1b + l*D, hh, hl);
        gemm_ws<4><<<gQKV, WS_THREADS, WS_SMEM>>>(hh, hl,
            wqh + (size_t)l*DQKV*D, wql + (size_t)l*DQKV*D,
            bqkv + l*DQKV, nullptr, nullptr, qh, qlo, M, DQKV, D);
        attn_tc<<<dim3(TSEQ/64, BATCH*NHEAD), 128, AT_SMEM>>>(qh, qlo, zh, zl);
        gemm_ws<2><<<gD, WS_THREADS, WS_SMEM>>>(zh, zl,
            woh + (size_t)l*d2, wol + (size_t)l*d2,
            bo + l*D, x, x, nullptr, nullptr, M, D, D);
        ln_split_k<<<M, 256>>>(x, l2g + l*D, l2b + l*D, hh, hl);
        gemm_ws<3><<<gM1, WS_THREADS, WS_SMEM>>>(hh, hl,
            w1h + (size_t)l*dm2, w1l + (size_t)l*dm2,
            b1 + l*DM, nullptr, nullptr, mh, ml, M, DM, D);
        gemm_ws<2><<<gD, WS_THREADS, WS_SMEM>>>(mh, ml,
            w2h + (size_t)l*dm2, w2l + (size_t)l*dm2,
            b2 + l*D, x, x, nullptr, nullptr, M, D, DM);
    }

    ln_split_k<<<M, 256>>>(x, lfg, lfb, hh, hl);
    gemm_ws<0><<<gLM, WS_THREADS, WS_SMEM>>>(hh, hl, wuh, wul,
        bu, nullptr, out, nullptr, nullptr, M, Vn, D);
}

// round 16
// speedup vs baseline: 1.0349x; 1.0349x over previous
#include <cuda_runtime.h>
#include <cuda_bf16.h>
#include <cstdint>
#include <cstddef>

// ---------------- problem constants ----------------
#define BATCH 2
#define TSEQ  1024
#define MROWS (BATCH*TSEQ)      // 2048
#define DMODEL 768
#define NHEAD 12
#define DHEAD 64
#define DMLP  3072
#define NLAYER 12
#define VOCAB 50257
#define DQKV  (3*DMODEL)        // 2304

// ---------------- scratch (static device globals; no allocation) ----------------
__device__ float g_x  [MROWS*DMODEL];          // residual stream (fp32)
__device__ __nv_bfloat16 g_qh[MROWS*DQKV],   g_qlo[MROWS*DQKV];    // qkv split
__device__ __nv_bfloat16 g_hh[MROWS*DMODEL], g_hl[MROWS*DMODEL];   // LN out split
__device__ __nv_bfloat16 g_zh[MROWS*DMODEL], g_zl[MROWS*DMODEL];   // attn out split
__device__ __nv_bfloat16 g_mh[MROWS*DMLP],   g_ml[MROWS*DMLP];     // MLP hidden split

// split+transposed weights, [N][K] K-major bf16 planes
__device__ __nv_bfloat16 g_wqkv_h[NLAYER*DQKV*DMODEL],  g_wqkv_l[NLAYER*DQKV*DMODEL];
__device__ __nv_bfloat16 g_wo_h  [NLAYER*DMODEL*DMODEL],g_wo_l  [NLAYER*DMODEL*DMODEL];
__device__ __nv_bfloat16 g_w1_h  [NLAYER*DMLP*DMODEL],  g_w1_l  [NLAYER*DMLP*DMODEL];
__device__ __nv_bfloat16 g_w2_h  [NLAYER*DMODEL*DMLP],  g_w2_l  [NLAYER*DMODEL*DMLP];
__device__ __nv_bfloat16 g_wu_h  [VOCAB*DMODEL],        g_wu_l  [VOCAB*DMODEL];
__device__ float g_bqkv[NLAYER*DQKV];

// ---------------- PTX helpers (plain sm_80+ features only) ----------------
__device__ __forceinline__ uint32_t smem_u32(const void* p){
    uint32_t a;
    asm("{ .reg .u64 t; cvta.to.shared.u64 t, %1; cvt.u32.u64 %0, t; }" : "=r"(a) : "l"(p));
    return a;
}
__device__ __forceinline__ void cpa16(uint32_t dst, const void* src, uint32_t srcsize){
    asm volatile("cp.async.cg.shared.global [%0], [%1], 16, %2;"
                 :: "r"(dst), "l"(src), "r"(srcsize) : "memory");
}
__device__ __forceinline__ void cpa_commit(){
    asm volatile("cp.async.commit_group;" ::: "memory");
}
__device__ __forceinline__ void cpa_wait1(){
    asm volatile("cp.async.wait_group 1;" ::: "memory");
}
__device__ __forceinline__ void cpa_wait0(){
    asm volatile("cp.async.wait_group 0;" ::: "memory");
}
__device__ __forceinline__ void ldsm4(uint32_t* r, uint32_t addr){
    asm volatile("ldmatrix.sync.aligned.m8n8.x4.shared.b16 {%0,%1,%2,%3}, [%4];"
                 : "=r"(r[0]), "=r"(r[1]), "=r"(r[2]), "=r"(r[3]) : "r"(addr));
}
__device__ __forceinline__ void ldsm4t(uint32_t* r, uint32_t addr){
    asm volatile("ldmatrix.sync.aligned.m8n8.x4.trans.shared.b16 {%0,%1,%2,%3}, [%4];"
                 : "=r"(r[0]), "=r"(r[1]), "=r"(r[2]), "=r"(r[3]) : "r"(addr));
}
__device__ __forceinline__ void mma_bf16(float* c, const uint32_t* a, const uint32_t* b){
    asm volatile("mma.sync.aligned.m16n8k16.row.col.f32.bf16.bf16.f32 "
                 "{%0,%1,%2,%3}, {%4,%5,%6,%7}, {%8,%9}, {%0,%1,%2,%3};"
                 : "+f"(c[0]), "+f"(c[1]), "+f"(c[2]), "+f"(c[3])
                 : "r"(a[0]), "r"(a[1]), "r"(a[2]), "r"(a[3]), "r"(b[0]), "r"(b[1]));
}
#define SMEM_SWIZZLE_128B(o) ((o) ^ (((o) >> 3) & 0x70))

// ---------------- small helpers ----------------
__device__ __forceinline__ float gelu_f(float x){
    return 0.5f * x * (1.0f + erff(x * 0.70710678118654752440f));
}
__device__ __forceinline__ void split2(float v, __nv_bfloat16& h, __nv_bfloat16& l){
    h = __float2bfloat16(v);
    l = __float2bfloat16(v - __bfloat162float(h));
}
__device__ __forceinline__ uint32_t pack_bf16(float a, float b){
    __nv_bfloat162 t = __floats2bfloat162_rn(a, b);   // low = a, high = b
    return *(uint32_t*)&t;
}

// ---------------- uber weight split+transpose (single launch) ----------------
// src[K][N] fp32 -> dst planes [N][K] bf16 (hi/lo), 32x32 tiles
__global__ void tsplit_all(const float* __restrict__ Wq, const float* __restrict__ Wk,
                           const float* __restrict__ Wv, const float* __restrict__ Wo,
                           const float* __restrict__ W1, const float* __restrict__ W2,
                           const float* __restrict__ Wu,
                           __nv_bfloat16* wqh, __nv_bfloat16* wql,
                           __nv_bfloat16* woh, __nv_bfloat16* wol,
                           __nv_bfloat16* w1h, __nv_bfloat16* w1l,
                           __nv_bfloat16* w2h, __nv_bfloat16* w2l,
                           __nv_bfloat16* wuh, __nv_bfloat16* wul)
{
    const int T0 = 24*24*12;          // 6912 tiles per D×D weight
    const int TW = 24*96*12;          // 27648 for W1 / W2
    int id = blockIdx.x;
    const float* src; __nv_bfloat16 *dh, *dl;
    long srcLS, dstLS; int rowOff = 0, ld, K, N;
    int l, kti, nti;
    if (id < 4*T0){
        int seg = id / T0, r = id % T0;
        l = r / 576; int r2 = r % 576; kti = r2 / 24; nti = r2 % 24;
        K = 768; N = 768; srcLS = 589824;
        if (seg < 3){
            src = (seg==0)?Wq:(seg==1)?Wk:Wv;
            dh = wqh; dl = wql; dstLS = 1769472; ld = 768; rowOff = seg*768;
        } else {
            src = Wo; dh = woh; dl = wol; dstLS = 589824; ld = 768;
        }
    } else if (id < 4*T0 + TW){
        int r = id - 4*T0;
        l = r / 2304; int r2 = r % 2304; kti = r2 / 96; nti = r2 % 96;
        src = W1; dh = w1h; dl = w1l; srcLS = 2359296; dstLS = 2359296;
        ld = 768; K = 768; N = 3072;
    } else if (id < 4*T0 + 2*TW){
        int r = id - 4*T0 - TW;
        l = r / 2304; int r2 = r % 2304; kti = r2 / 24; nti = r2 % 24;
        src = W2; dh = w2h; dl = w2l; srcLS = 2359296; dstLS = 2359296;
        ld = 3072; K = 3072; N = 768;
    } else {
        int r = id - 4*T0 - 2*TW;
        l = 0; kti = r / 1571; nti = r % 1571;
        src = Wu; dh = wuh; dl = wul; srcLS = 0; dstLS = 0;
        ld = 768; K = 768; N = VOCAB;
    }
    const int k0 = kti*32, n0 = nti*32;
    __shared__ float t[32][33];
    int tx = threadIdx.x & 31, ty = threadIdx.x >> 5;
    const float* s = src + (size_t)l * srcLS;
    #pragma unroll
    for (int i = ty; i < 32; i += 8){
        int k = k0 + i, n = n0 + tx;
        t[i][tx] = (k < K && n < N) ? s[(size_t)k * N + n] : 0.f;
    }
    __syncthreads();
    __nv_bfloat16* ph = dh + (size_t)l * dstLS;
    __nv_bfloat16* pl = dl + (size_t)l * dstLS;
    #pragma unroll
    for (int i = ty; i < 32; i += 8){
        int n = n0 + i, k = k0 + tx;
        if (n < N && k < K){
            float v = t[tx][i];
            __nv_bfloat16 h, lo; split2(v, h, lo);
            size_t off = (size_t)(rowOff + n) * ld + k;
            ph[off] = h; pl[off] = lo;
        }
    }
}

__global__ void bcat_k(const float* __restrict__ bq, const float* __restrict__ bk,
                       const float* __restrict__ bv, float* __restrict__ dst)
{
    int l = blockIdx.y;
    int i = blockIdx.x * 256 + threadIdx.x;
    if (i < DQKV){
        float v = (i < 768) ? bq[l*768 + i] : (i < 1536) ? bk[l*768 + i - 768]
                                                         : bv[l*768 + i - 1536];
        dst[l*DQKV + i] = v;
    }
}

// ---------------- embedding ----------------
__global__ void embed_k(const int* __restrict__ ids, const float* __restrict__ emb,
                        const float* __restrict__ pos, float* __restrict__ x)
{
    int row = blockIdx.x, t = row % TSEQ, id = ids[row];
    const float* er = emb + (size_t)id * DMODEL;
    const float* pr = pos + (size_t)t  * DMODEL;
    float* xr = x + (size_t)row * DMODEL;
    int tid = threadIdx.x;
    xr[tid]       = er[tid]       + pr[tid];
    xr[tid + 256] = er[tid + 256] + pr[tid + 256];
    xr[tid + 512] = er[tid + 512] + pr[tid + 512];
}

// ---------------- layernorm -> bf16 hi/lo split ----------------
__global__ void ln_split_k(const float* __restrict__ x, const float* __restrict__ g,
                           const float* __restrict__ b,
                           __nv_bfloat16* __restrict__ oh, __nv_bfloat16* __restrict__ ol)
{
    __shared__ float red0[8], red1[8];
    int row = blockIdx.x, tid = threadIdx.x;
    const float* xr = x + (size_t)row * DMODEL;
    float v0 = xr[tid], v1 = xr[tid + 256], v2 = xr[tid + 512];
    float s  = v0 + v1 + v2;
    float s2 = v0*v0 + v1*v1 + v2*v2;
    #pragma unroll
    for (int off = 16; off; off >>= 1){
        s  += __shfl_xor_sync(0xffffffffu, s,  off);
        s2 += __shfl_xor_sync(0xffffffffu, s2, off);
    }
    int w = tid >> 5;
    if ((tid & 31) == 0){ red0[w] = s; red1[w] = s2; }
    __syncthreads();
    if (tid < 32){
        s  = (tid < 8) ? red0[tid] : 0.f;
        s2 = (tid < 8) ? red1[tid] : 0.f;
        #pragma unroll
        for (int off = 4; off; off >>= 1){
            s  += __shfl_xor_sync(0xffffffffu, s,  off);
            s2 += __shfl_xor_sync(0xffffffffu, s2, off);
        }
        if (tid == 0){ red0[0] = s; red1[0] = s2; }
    }
    __syncthreads();
    float mean = red0[0] * (1.f/768.f);
    float var  = red1[0] * (1.f/768.f) - mean * mean;
    float r    = rsqrtf(var + 1e-5f);
    size_t base = (size_t)row * DMODEL;
    #pragma unroll
    for (int e = 0; e < 3; ++e){
        int idx = tid + e*256;
        float vv = (e==0?v0:(e==1?v1:v2));
        float y = (vv - mean) * r * g[idx] + b[idx];
        __nv_bfloat16 h, lo; split2(y, h, lo);
        oh[base + idx] = h; ol[base + idx] = lo;
    }
}

// ---------------- mma.sync bf16-split GEMM (8 warps, 64x32 warp tile) ----------------
// C[M,N] = epi( (Ah+Al) * (Bh+Bl)^T + bias )   A:[M][K] planes, B:[N][K] planes.
// Grid: blockIdx.x = m-block, blockIdx.y = n-block  (m fastest -> B tiles L2-shared)
// EPI: 0 = fp32 out ; 2 = fp32 out + residual ; 3 = GELU -> bf16 split out ;
//      4 = bias only -> bf16 split out
#define WS_THREADS 256
#define WS_NSTAGE 3
#define WS_STAGE_BYTES 65536          // 4 buffers (Ah,Al,Bh,Bl) x 16KB each
#define WS_SMEM (WS_NSTAGE*WS_STAGE_BYTES)

template<int EPI>
__global__ __launch_bounds__(WS_THREADS, 1)
void gemm_ws(const __nv_bfloat16* __restrict__ Ah, const __nv_bfloat16* __restrict__ Al,
             const __nv_bfloat16* __restrict__ Bh, const __nv_bfloat16* __restrict__ Bl,
             const float* __restrict__ bias, const float* __restrict__ res,
             float* __restrict__ C, __nv_bfloat16* __restrict__ Ch,
             __nv_bfloat16* __restrict__ Cl, int M, int N, int K)
{
    extern __shared__ char smem[];
    const uint32_t sb = smem_u32(smem);
    const int tid = threadIdx.x, wid = tid >> 5, lane = tid & 31;
    const int warp_m = wid & 1;        // 0..1 -> 64 rows each
    const int warp_n = wid >> 1;       // 0..3 -> 32 cols each
    const int m0 = blockIdx.x * 128, n0 = blockIdx.y * 128;   // m fastest

    float acc[16][4];
    #pragma unroll
    for (int i = 0; i < 16; i++)
        #pragma unroll
        for (int j = 0; j < 4; j++) acc[i][j] = 0.f;

    const int nch = K >> 6;

    auto load_stage = [&](int st, int k0){
        const uint32_t s0 = sb + (uint32_t)st * WS_STAGE_BYTES;
        #pragma unroll
        for (int it = 0; it < 4; ++it){
            int idx = it * 256 + tid;            // 0..1023
            int row = idx >> 3, ch = idx & 7;
            uint32_t off = SMEM_SWIZZLE_128B(row*128 + ch*16);
            const size_t aoff = (size_t)(m0 + row) * K + k0 + ch*8;
            cpa16(s0 +         off, Ah + aoff, 16);
            cpa16(s0 + 16384 + off, Al + aoff, 16);
            int brow = n0 + row;
            uint32_t sz = (brow < N) ? 16u : 0u;
            if (brow >= N) brow = N - 1;
            const size_t boff = (size_t)brow * K + k0 + ch*8;
            cpa16(s0 + 32768 + off, Bh + boff, sz);
            cpa16(s0 + 49152 + off, Bl + boff, sz);
        }
        cpa_commit();
    };

    auto compute_stage = [&](int st){
        const uint32_t sAh = sb + (uint32_t)st * WS_STAGE_BYTES;
        const uint32_t sAl = sAh + 16384;
        const uint32_t sBh = sAh + 32768;
        const uint32_t sBl = sAh + 49152;
        #pragma unroll
        for (int ks = 0; ks < 4; ++ks){
            uint32_t ah[4][4], al[4][4], bh[4][2], bl[4][2];
            const int arow = warp_m*64 + (lane & 7) + ((lane >> 3) & 1) * 8;
            const int akc  = ks*16 + ((lane >> 4) & 1) * 8;
            #pragma unroll
            for (int mt = 0; mt < 4; ++mt){
                uint32_t off = SMEM_SWIZZLE_128B((arow + mt*16)*128 + akc*2);
                ldsm4(ah[mt], sAh + off);
                ldsm4(al[mt], sAl + off);
            }
            const int brow0 = warp_n*32 + ((lane >> 4) & 1) * 8 + (lane & 7);
            const int bkc   = ks*16 + ((lane >> 3) & 1) * 8;
            #pragma unroll
            for (int nq = 0; nq < 2; ++nq){
                uint32_t off = SMEM_SWIZZLE_128B((brow0 + nq*16)*128 + bkc*2);
                uint32_t r[4];
                ldsm4(r, sBh + off);
                bh[2*nq][0] = r[0]; bh[2*nq][1] = r[1];
                bh[2*nq+1][0] = r[2]; bh[2*nq+1][1] = r[3];
                ldsm4(r, sBl + off);
                bl[2*nq][0] = r[0]; bl[2*nq][1] = r[1];
                bl[2*nq+1][0] = r[2]; bl[2*nq+1][1] = r[3];
            }
            #pragma unroll
            for (int mt = 0; mt < 4; ++mt)
                #pragma unroll
                for (int nt = 0; nt < 4; ++nt){
                    float* c = acc[mt*4 + nt];
                    mma_bf16(c, ah[mt], bh[nt]);
                    mma_bf16(c, ah[mt], bl[nt]);
                    mma_bf16(c, al[mt], bh[nt]);
                }
        }
    };

    load_stage(0, 0);
    load_stage(1, 64);
    for (int c = 0; c < nch; ++c){
        if (c + 1 < nch) cpa_wait1(); else cpa_wait0();
        __syncthreads();
        int p = c + WS_NSTAGE - 1;
        if (p < nch) load_stage(p % WS_NSTAGE, p * 64);
        else cpa_commit();
        compute_stage(c % WS_NSTAGE);
    }

    const int lr = lane >> 2, lc = (lane & 3) * 2;
    const bool nvec = ((N & 1) == 0);
    #pragma unroll
    for (int mt = 0; mt < 4; ++mt){
        #pragma unroll
        for (int nt = 0; nt < 4; ++nt){
            const float* cfr = acc[mt*4 + nt];
            const int n = n0 + warp_n*32 + nt*8 + lc;
            #pragma unroll
            for (int half = 0; half < 2; ++half){
                const int m = m0 + warp_m*64 + mt*16 + lr + half*8;
                float v0 = cfr[half*2 + 0];
                float v1 = cfr[half*2 + 1];
                if (EPI == 3 || EPI == 4){
                    v0 += bias[n]; v1 += bias[n+1];
                    if (EPI == 3){ v0 = gelu_f(v0); v1 = gelu_f(v1); }
                    __nv_bfloat16 h0, l0, h1, l1;
                    split2(v0, h0, l0); split2(v1, h1, l1);
                    __nv_bfloat162 hp; hp.x = h0; hp.y = h1;
                    __nv_bfloat162 lp; lp.x = l0; lp.y = l1;
                    *(__nv_bfloat162*)(Ch + (size_t)m * N + n) = hp;
                    *(__nv_bfloat162*)(Cl + (size_t)m * N + n) = lp;
                } else {
                    if (n < N) v0 += bias[n];
                    if (n + 1 < N) v1 += bias[n+1];
                    if (EPI == 2){
                        const float2 r2 = *(const float2*)(res + (size_t)m * N + n);
                        v0 += r2.x; v1 += r2.y;
                    }
                    if (nvec && (n + 1 < N)){
                        float2 o2; o2.x = v0; o2.y = v1;
                        *(float2*)(C + (size_t)m * N + n) = o2;
                    } else {
                        if (n < N)     C[(size_t)m * N + n]     = v0;
                        if (n + 1 < N) C[(size_t)m * N + n + 1] = v1;
                    }
                }
            }
        }
    }
}

// ---------------- tensor-core flash attention (bf16 hi/lo split, 3-pass) ----------------
// Input: qkv planes [M][2304] (hi/lo). Output: Z planes [M][768] (hi/lo).
// CTA: 64 q rows, 4 warps x 16 rows. KV tiles of 64. smem = 48KB.
#define AT_SMEM 49152
__global__ __launch_bounds__(128)
void attn_tc(const __nv_bfloat16* __restrict__ Xh, const __nv_bfloat16* __restrict__ Xl,
             __nv_bfloat16* __restrict__ Zh, __nv_bfloat16* __restrict__ Zl)
{
    extern __shared__ char sm[];
    const uint32_t sb = smem_u32(sm);
    // layout: Qh 0, Ql 8192, Kh 16384, Kl 24576, Vh 32768, Vl 40960
    const int tid = threadIdx.x, warp = tid >> 5, lane = tid & 31;
    const int qt = blockIdx.x, bh = blockIdx.y;
    const int b = bh / NHEAD, h = bh % NHEAD;
    const int q0 = qt * 64;
    const size_t rowbase = (size_t)b * TSEQ;
    const int colQ = h*DHEAD, colK = DMODEL + h*DHEAD, colV = 2*DMODEL + h*DHEAD;

    // load Q tile (hi/lo)
    #pragma unroll
    for (int it = 0; it < 4; ++it){
        int idx = it*128 + tid;
        int r = idx >> 3, ch = idx & 7;
        uint32_t off = SMEM_SWIZZLE_128B(r*128 + ch*16);
        size_t go = (rowbase + q0 + r) * (size_t)DQKV + colQ + ch*8;
        cpa16(sb +        off, Xh + go, 16);
        cpa16(sb + 8192 + off, Xl + go, 16);
    }
    cpa_commit();

    float mst[2] = {-1e30f, -1e30f}, lst[2] = {0.f, 0.f};
    float zacc[8][4];
    #pragma unroll
    for (int j = 0; j < 8; j++)
        #pragma unroll
        for (int i = 0; i < 4; i++) zacc[j][i] = 0.f;

    cpa_wait0();
    __syncthreads();

    // Q fragments (A operand), 4 k16 slices, hi/lo
    uint32_t qh[4][4], ql[4][4];
    {
        const int arow = warp*16 + (lane & 7) + ((lane >> 3) & 1) * 8;
        #pragma unroll
        for (int ks = 0; ks < 4; ++ks){
            int akc = ks*16 + ((lane >> 4) & 1) * 8;
            uint32_t off = SMEM_SWIZZLE_128B(arow*128 + akc*2);
            ldsm4(qh[ks], sb +        off);
            ldsm4(ql[ks], sb + 8192 + off);
        }
    }

    const int nkt = qt + 1;
    for (int kt = 0; kt < nkt; ++kt){
        const int k0 = kt * 64;
        __syncthreads();          // previous tile's ldsm reads done
        #pragma unroll
        for (int it = 0; it < 4; ++it){
            int idx = it*128 + tid;
            int r = idx >> 3, ch = idx & 7;
            uint32_t off = SMEM_SWIZZLE_128B(r*128 + ch*16);
            size_t gk = (rowbase + k0 + r) * (size_t)DQKV + colK + ch*8;
            size_t gv = (rowbase + k0 + r) * (size_t)DQKV + colV + ch*8;
            cpa16(sb + 16384 + off, Xh + gk, 16);
            cpa16(sb + 24576 + off, Xl + gk, 16);
            cpa16(sb + 32768 + off, Xh + gv, 16);
            cpa16(sb + 40960 + off, Xl + gv, 16);
        }
        cpa_commit(); cpa_wait0();
        __syncthreads();

        // ---- S = Q K^T (3-pass split), per warp: 16 x 64 ----
        float sacc[8][4];
        #pragma unroll
        for (int j = 0; j < 8; j++)
            #pragma unroll
            for (int i = 0; i < 4; i++) sacc[j][i] = 0.f;

        #pragma unroll
        for (int ks = 0; ks < 4; ++ks){
            uint32_t bhf[8][2], blf[8][2];
            const int brow = ((lane >> 4) & 1) * 8 + (lane & 7);
            const int bkc  = ks*16 + ((lane >> 3) & 1) * 8;
            #pragma unroll
            for (int nq = 0; nq < 4; ++nq){
                uint32_t off = SMEM_SWIZZLE_128B((nq*16 + brow)*128 + bkc*2);
                uint32_t r[4];
                ldsm4(r, sb + 16384 + off);
                bhf[2*nq][0] = r[0]; bhf[2*nq][1] = r[1];
                bhf[2*nq+1][0] = r[2]; bhf[2*nq+1][1] = r[3];
                ldsm4(r, sb + 24576 + off);
                blf[2*nq][0] = r[0]; blf[2*nq][1] = r[1];
                blf[2*nq+1][0] = r[2]; blf[2*nq+1][1] = r[3];
            }
            #pragma unroll
            for (int j = 0; j < 8; j++){
                mma_bf16(sacc[j], qh[ks], bhf[j]);
                mma_bf16(sacc[j], qh[ks], blf[j]);
                mma_bf16(sacc[j], ql[ks], bhf[j]);
            }
        }

        // ---- scale + causal mask ----
        const bool diag = (kt == qt);
        const int r0g = q0 + warp*16 + (lane >> 2);
        #pragma unroll
        for (int j = 0; j < 8; j++){
            const int kg = k0 + j*8 + (lane & 3)*2;
            #pragma unroll
            for (int i = 0; i < 4; i++){
                float v = sacc[j][i] * 0.125f;
                if (diag){
                    int kk = kg + (i & 1);
                    int qq = r0g + ((i >= 2) ? 8 : 0);
                    if (kk > qq) v = -1e30f;
                }
                sacc[j][i] = v;
            }
        }

        // ---- online softmax (rows r0, r0+8; reduce over 4-lane col groups) ----
        #pragma unroll
        for (int t = 0; t < 2; ++t){
            float mx = -1e30f;
            #pragma unroll
            for (int j = 0; j < 8; j++)
                mx = fmaxf(mx, fmaxf(sacc[j][2*t], sacc[j][2*t+1]));
            mx = fmaxf(mx, __shfl_xor_sync(0xffffffffu, mx, 1));
            mx = fmaxf(mx, __shfl_xor_sync(0xffffffffu, mx, 2));
            float mn = fmaxf(mst[t], mx);
            float corr = expf(mst[t] - mn);
            mst[t] = mn;
            float rs = 0.f;
            #pragma unroll
            for (int j = 0; j < 8; j++){
                float p0 = expf(sacc[j][2*t]   - mn);
                float p1 = expf(sacc[j][2*t+1] - mn);
                sacc[j][2*t] = p0; sacc[j][2*t+1] = p1;
                rs += p0 + p1;
            }
            rs += __shfl_xor_sync(0xffffffffu, rs, 1);
            rs += __shfl_xor_sync(0xffffffffu, rs, 2);
            lst[t] = lst[t] * corr + rs;
            #pragma unroll
            for (int j = 0; j < 8; j++){
                zacc[j][2*t]   *= corr;
                zacc[j][2*t+1] *= corr;
            }
        }

        // ---- Z += P V  (P split in registers, V via ldsm.trans; 3-pass) ----
        #pragma unroll
        for (int ks2 = 0; ks2 < 4; ++ks2){
            // P fragments from sacc (C-layout -> A-layout identity)
            uint32_t ph[4], pl[4];
            {
                const float* s0 = sacc[2*ks2];
                const float* s1 = sacc[2*ks2+1];
                __nv_bfloat162 h0 = __floats2bfloat162_rn(s0[0], s0[1]);
                __nv_bfloat162 h1 = __floats2bfloat162_rn(s0[2], s0[3]);
                __nv_bfloat162 h2 = __floats2bfloat162_rn(s1[0], s1[1]);
                __nv_bfloat162 h3 = __floats2bfloat162_rn(s1[2], s1[3]);
                ph[0] = *(uint32_t*)&h0; ph[1] = *(uint32_t*)&h1;
                ph[2] = *(uint32_t*)&h2; ph[3] = *(uint32_t*)&h3;
                pl[0] = pack_bf16(s0[0] - __bfloat162float(h0.x), s0[1] - __bfloat162float(h0.y));
                pl[1] = pack_bf16(s0[2] - __bfloat162float(h1.x), s0[3] - __bfloat162float(h1.y));
                pl[2] = pack_bf16(s1[0] - __bfloat162float(h2.x), s1[1] - __bfloat162float(h2.y));
                pl[3] = pack_bf16(s1[2] - __bfloat162float(h3.x), s1[3] - __bfloat162float(h3.y));
            }
            // V fragments (B operand, n=d, k=kv) via trans loads from Vs[kv][d]
            uint32_t vh[8][2], vl[8][2];
            const int vrow = ks2*16 + ((lane >> 3) & 1) * 8 + (lane & 7);
            const int vcb  = ((lane >> 4) & 1) * 8;
            #pragma unroll
            for (int nq = 0; nq < 4; ++nq){
                uint32_t off = SMEM_SWIZZLE_128B(vrow*128 + (nq*16 + vcb)*2);
                uint32_t r[4];
                ldsm4t(r, sb + 32768 + off);
                vh[2*nq][0] = r[0]; vh[2*nq][1] = r[1];
                vh[2*nq+1][0] = r[2]; vh[2*nq+1][1] = r[3];
                ldsm4t(r, sb + 40960 + off);
                vl[2*nq][0] = r[0]; vl[2*nq][1] = r[1];
                vl[2*nq+1][0] = r[2]; vl[2*nq+1][1] = r[3];
            }
            #pragma unroll
            for (int j = 0; j < 8; j++){
                mma_bf16(zacc[j], ph, vh[j]);
                mma_bf16(zacc[j], ph, vl[j]);
                mma_bf16(zacc[j], pl, vh[j]);
            }
        }
    }

    // ---- normalize + write Z as bf16 hi/lo planes [M][768] ----
    #pragma unroll
    for (int t = 0; t < 2; ++t){
        float inv = 1.f / lst[t];
        int qg = q0 + warp*16 + (lane >> 2) + t*8;
        size_t ob = (rowbase + qg) * (size_t)DMODEL + h*DHEAD;
        #pragma unroll
        for (int j = 0; j < 8; j++){
            int d = j*8 + (lane & 3)*2;
            float z0 = zacc[j][2*t]   * inv;
            float z1 = zacc[j][2*t+1] * inv;
            __nv_bfloat16 h0, l0, h1, l1;
            split2(z0, h0, l0); split2(z1, h1, l1);
            __nv_bfloat162 hp; hp.x = h0; hp.y = h1;
            __nv_bfloat162 lp; lp.x = l0; lp.y = l1;
            *(__nv_bfloat162*)(Zh + ob + d) = hp;
            *(__nv_bfloat162*)(Zl + ob + d) = lp;
        }
    }
}

// ---------------- host orchestration ----------------
extern "C" void kernel_launch(void* const* d_in, const int* in_sizes, int n_in,
                              void* d_out, int out_size)
{
    const int*   ids = (const int*)  d_in[0];
    const float* emb = (const float*)d_in[1];
    const float* pos = (const float*)d_in[2];
    const float* Wq  = (const float*)d_in[3],  *bq = (const float*)d_in[4];
    const float* Wk  = (const float*)d_in[5],  *bk = (const float*)d_in[6];
    const float* Wv  = (const float*)d_in[7],  *bv = (const float*)d_in[8];
    const float* Wo  = (const float*)d_in[9],  *bo = (const float*)d_in[10];
    const float* l1g = (const float*)d_in[11], *l1b = (const float*)d_in[12];
    const float* l2g = (const float*)d_in[13], *l2b = (const float*)d_in[14];
    const float* W1  = (const float*)d_in[15], *b1 = (const float*)d_in[16];
    const float* W2  = (const float*)d_in[17], *b2 = (const float*)d_in[18];
    const float* lfg = (const float*)d_in[19], *lfb = (const float*)d_in[20];
    const float* Wu  = (const float*)d_in[21], *bu = (const float*)d_in[22];
    float* out = (float*)d_out;

    float *x, *bqkv;
    __nv_bfloat16 *qh, *qlo, *hh, *hl, *zh, *zl, *mh, *ml;
    __nv_bfloat16 *wqh, *wql, *woh, *wol, *w1h, *w1l, *w2h, *w2l, *wuh, *wul;
    cudaGetSymbolAddress((void**)&x,    g_x);
    cudaGetSymbolAddress((void**)&bqkv, g_bqkv);
    cudaGetSymbolAddress((void**)&qh,   g_qh);  cudaGetSymbolAddress((void**)&qlo, g_qlo);
    cudaGetSymbolAddress((void**)&hh,   g_hh);  cudaGetSymbolAddress((void**)&hl, g_hl);
    cudaGetSymbolAddress((void**)&zh,   g_zh);  cudaGetSymbolAddress((void**)&zl, g_zl);
    cudaGetSymbolAddress((void**)&mh,   g_mh);  cudaGetSymbolAddress((void**)&ml, g_ml);
    cudaGetSymbolAddress((void**)&wqh,  g_wqkv_h); cudaGetSymbolAddress((void**)&wql, g_wqkv_l);
    cudaGetSymbolAddress((void**)&woh,  g_wo_h);   cudaGetSymbolAddress((void**)&wol, g_wo_l);
    cudaGetSymbolAddress((void**)&w1h,  g_w1_h);   cudaGetSymbolAddress((void**)&w1l, g_w1_l);
    cudaGetSymbolAddress((void**)&w2h,  g_w2_h);   cudaGetSymbolAddress((void**)&w2l, g_w2_l);
    cudaGetSymbolAddress((void**)&wuh,  g_wu_h);   cudaGetSymbolAddress((void**)&wul, g_wu_l);

    cudaFuncSetAttribute(gemm_ws<0>, cudaFuncAttributeMaxDynamicSharedMemorySize, WS_SMEM);
    cudaFuncSetAttribute(gemm_ws<2>, cudaFuncAttributeMaxDynamicSharedMemorySize, WS_SMEM);
    cudaFuncSetAttribute(gemm_ws<3>, cudaFuncAttributeMaxDynamicSharedMemorySize, WS_SMEM);
    cudaFuncSetAttribute(gemm_ws<4>, cudaFuncAttributeMaxDynamicSharedMemorySize, WS_SMEM);
    cudaFuncSetAttribute(attn_tc,    cudaFuncAttributeMaxDynamicSharedMemorySize, AT_SMEM);

    const int M = MROWS, D = DMODEL, DM = DMLP, Vn = VOCAB;
    const size_t d2 = (size_t)D * D, dm2 = (size_t)D * DM;

    // single-launch weight split (tiles: 4*6912 + 2*27648 + 37704 = 120648)
    tsplit_all<<<120648, 256>>>(Wq, Wk, Wv, Wo, W1, W2, Wu,
                                wqh, wql, woh, wol, w1h, w1l, w2h, w2l, wuh, wul);
    bcat_k<<<dim3((DQKV + 255)/256, NLAYER), 256>>>(bq, bk, bv, bqkv);
    embed_k<<<M, 256>>>(ids, emb, pos, x);

    // grids: x = m-blocks (16), y = n-blocks  -> B tile shared across a wave
    const dim3 gQKV(M/128, DQKV/128);      // (16,18)
    const dim3 gD  (M/128, D/128);         // (16,6)
    const dim3 gM1 (M/128, DM/128);        // (16,24)
    const dim3 gLM (M/128, (Vn + 127)/128);// (16,393)

    for (int l = 0; l < NLAYER; ++l){
        ln_split_k<<<M, 256>>>(x, l1g + l*D, l1b + l*D, hh, hl);
        gemm_ws<4><<<gQKV, WS_THREADS, WS_SMEM>>>(hh, hl,
            wqh + (size_t)l*DQKV*D, wql + (size_t)l*DQKV*D,
            bqkv + l*DQKV, nullptr, nullptr, qh, qlo, M, DQKV, D);
        attn_tc<<<dim3(TSEQ/64, BATCH*NHEAD), 128, AT_SMEM>>>(qh, qlo, zh, zl);
        gemm_ws<2><<<gD, WS_THREADS, WS_SMEM>>>(zh, zl,
            woh + (size_t)l*d2, wol + (size_t)l*d2,
            bo + l*D, x, x, nullptr, nullptr, M, D, D);
        ln_split_k<<<M, 256>>>(x, l2g + l*D, l2b + l*D, hh, hl);
        gemm_ws<3><<<gM1, WS_THREADS, WS_SMEM>>>(hh, hl,
            w1h + (size_t)l*dm2, w1l + (size_t)l*dm2,
            b1 + l*DM, nullptr, nullptr, mh, ml, M, DM, D);
        gemm_ws<2><<<gD, WS_THREADS, WS_SMEM>>>(mh, ml,
            w2h + (size_t)l*dm2, w2l + (size_t)l*dm2,
            b2 + l*D, x, x, nullptr, nullptr, M, D, DM);
    }

    ln_split_k<<<M, 256>>>(x, lfg, lfb, hh, hl);
    gemm_ws<0><<<gLM, WS_THREADS, WS_SMEM>>>(hh, hl, wuh, wul,
        bu, nullptr, out, nullptr, nullptr, M, Vn, D);
}